// round 8
// baseline (speedup 1.0000x reference)
#include <cuda_runtime.h>
#include <cuda_bf16.h>

#define Bn   8
#define Cn   256
#define Gn   32
#define Hn   56
#define Wn   56
#define HWn  3136        // 56*56
#define QW   14          // float4 quads per row
#define NPART 4          // channel-pairs per (b,g,h,q)
#define NCH   2          // channels per thread
#define TOTAL_THREADS (Bn*Gn*Hn*QW*NPART)   // 802816

__global__ __launch_bounds__(128, 5)
void SKA_20950850470021_kernel(const float* __restrict__ x,
                               const float* __restrict__ w,
                               float* __restrict__ out) {
    int idx = blockIdx.x * blockDim.x + threadIdx.x;

    // p second-innermost: the 4 channel-pair threads sharing one weight quad
    // sit in adjacent lanes of the same warp/block -> w loads broadcast in L1.
    int q = idx % QW;
    int t = idx / QW;
    int p = t % NPART;       // 0..3 : which pair of channels
    t /= NPART;
    int h = t % Hn;
    t /= Hn;
    int g = t % Gn;
    int b = t / Gn;

    const int w0 = q * 4;
    const float hasLf = (q > 0) ? 1.f : 0.f;
    const float hasRf = (q < QW - 1) ? 1.f : 0.f;
    const int   dL = (q > 0) ? -1 : 0;          // safe left-edge offset
    const int   dR = (q < QW - 1) ? 4 : 0;      // safe right-edge offset

    // row validity (r = 0,1,2 -> hh = h-1, h, h+1); clamp offset for safe loads
    const float fv[3] = { (h > 0) ? 1.f : 0.f, 1.f, (h < Hn - 1) ? 1.f : 0.f };
    const int roff[3] = { (h > 0) ? -Wn : 0, 0, (h < Hn - 1) ? Wn : 0 };

    // ---------------- load phase: everything front-batched ----------------
    const float* wbase = w + ((b * Gn + g) * 9) * HWn + h * Wn + w0;
    float4 wk[9];
#pragma unroll
    for (int k = 0; k < 9; ++k)
        wk[k] = *reinterpret_cast<const float4*>(wbase + k * HWn);

    const int base = (b * Cn + g) * HWn + h * Wn + w0;
    float4 cen[NCH][3];
    float  lf [NCH][3];
    float  rf [NCH][3];
#pragma unroll
    for (int j = 0; j < NCH; ++j) {
        const float* xc = x + base + (p * NCH + j) * Gn * HWn;
#pragma unroll
        for (int r = 0; r < 3; ++r) {
            const float* xr = xc + roff[r];
            cen[j][r] = *reinterpret_cast<const float4*>(xr);
            lf [j][r] = xr[dL];
            rf [j][r] = xr[dR];
        }
    }

    // ---------------- compute phase ----------------
    // fold row validity into the weights (shared by both channels),
    // and edge validity into the edge scalars.
#pragma unroll
    for (int k = 0; k < 9; ++k) {
        const float s = fv[k / 3];
        wk[k].x *= s; wk[k].y *= s; wk[k].z *= s; wk[k].w *= s;
    }
#pragma unroll
    for (int j = 0; j < NCH; ++j)
#pragma unroll
        for (int r = 0; r < 3; ++r) {
            lf[j][r] *= hasLf;
            rf[j][r] *= hasRf;
        }

    float4 acc[NCH];
#pragma unroll
    for (int j = 0; j < NCH; ++j) {
        float4 a = make_float4(0.f, 0.f, 0.f, 0.f);
#pragma unroll
        for (int r = 0; r < 3; ++r) {
            const float4 wk0 = wk[r * 3 + 0];
            const float4 wk1 = wk[r * 3 + 1];
            const float4 wk2 = wk[r * 3 + 2];
            const float4 c = cen[j][r];
            a.x += lf[j][r] * wk0.x + c.x * wk1.x + c.y * wk2.x;
            a.y += c.x * wk0.y + c.y * wk1.y + c.z * wk2.y;
            a.z += c.y * wk0.z + c.z * wk1.z + c.w * wk2.z;
            a.w += c.z * wk0.w + c.w * wk1.w + rf[j][r] * wk2.w;
        }
        acc[j] = a;
    }

#pragma unroll
    for (int j = 0; j < NCH; ++j)
        *reinterpret_cast<float4*>(out + base + (p * NCH + j) * Gn * HWn) = acc[j];
}

extern "C" void kernel_launch(void* const* d_in, const int* in_sizes, int n_in,
                              void* d_out, int out_size) {
    const float* x = (const float*)d_in[0];   // (8,256,56,56)
    const float* w = (const float*)d_in[1];   // (8,32,9,56,56)
    float* out = (float*)d_out;               // (8,256,56,56)

    const int threads = 128;
    const int blocks = TOTAL_THREADS / threads;  // 6272
    SKA_20950850470021_kernel<<<blocks, threads>>>(x, w, out);
}

// round 9
// speedup vs baseline: 1.2429x; 1.2429x over previous
#include <cuda_runtime.h>
#include <cuda_bf16.h>

#define Bn   8
#define Cn   256
#define Gn   32
#define Hn   56
#define Wn   56
#define HWn  3136        // 56*56
#define QW   14          // float4 quads per row
#define NPART 4          // channel-pairs per (b,g,h,q)
#define NCH   2          // channels per thread
#define TOTAL_THREADS (Bn*Gn*Hn*QW*NPART)   // 802816

__global__ __launch_bounds__(128, 5)
void SKA_20950850470021_kernel(const float* __restrict__ x,
                               const float* __restrict__ w,
                               float* __restrict__ out) {
    int idx = blockIdx.x * blockDim.x + threadIdx.x;

    int q = idx % QW;
    int t = idx / QW;
    int h = t % Hn;
    t /= Hn;
    int g = t % Gn;
    t /= Gn;
    int b = t % Bn;
    int p = t / Bn;          // 0..3 : which pair of channels

    const int lane = threadIdx.x & 31;
    const int w0 = q * 4;
    const float hasLf = (q > 0) ? 1.f : 0.f;
    const float hasRf = (q < QW - 1) ? 1.f : 0.f;

    // row validity (r = 0,1,2 -> hh = h-1, h, h+1); clamp offset for safe loads
    const float fv[3] = { (h > 0) ? 1.f : 0.f, 1.f, (h < Hn - 1) ? 1.f : 0.f };
    const int roff[3] = { (h > 0) ? -Wn : 0, 0, (h < Hn - 1) ? Wn : 0 };

    // warp-boundary lanes must fetch their halo scalar for real
    const bool needL = (lane == 0)  && (q > 0);
    const bool needR = (lane == 31) && (q < QW - 1);

    // ---------------- load phase: everything front-batched ----------------
    const float* wbase = w + ((b * Gn + g) * 9) * HWn + h * Wn + w0;
    float4 wk[9];
#pragma unroll
    for (int k = 0; k < 9; ++k)
        wk[k] = *reinterpret_cast<const float4*>(wbase + k * HWn);

    const int base = (b * Cn + g) * HWn + h * Wn + w0;
    float4 cen[NCH][3];
    float  lfx[NCH][3];
    float  rfx[NCH][3];
#pragma unroll
    for (int j = 0; j < NCH; ++j) {
        const float* xc = x + base + (p * NCH + j) * Gn * HWn;
#pragma unroll
        for (int r = 0; r < 3; ++r) {
            const float* xr = xc + roff[r];
            cen[j][r] = *reinterpret_cast<const float4*>(xr);
            lfx[j][r] = needL ? xr[-1] : 0.f;   // single-lane predicated loads
            rfx[j][r] = needR ? xr[4]  : 0.f;
        }
    }

    // ---------------- halo via warp shuffle (no L1 traffic) ----------------
    float lf[NCH][3], rf[NCH][3];
#pragma unroll
    for (int j = 0; j < NCH; ++j)
#pragma unroll
        for (int r = 0; r < 3; ++r) {
            float lv = __shfl_up_sync(0xFFFFFFFFu, cen[j][r].w, 1);
            float rv = __shfl_down_sync(0xFFFFFFFFu, cen[j][r].x, 1);
            if (lane == 0)  lv = lfx[j][r];
            if (lane == 31) rv = rfx[j][r];
            // hasLf/hasRf zero both true borders and cross-row shuffle garbage
            lf[j][r] = lv * hasLf;
            rf[j][r] = rv * hasRf;
        }

    // ---------------- compute phase ----------------
#pragma unroll
    for (int k = 0; k < 9; ++k) {
        const float s = fv[k / 3];
        wk[k].x *= s; wk[k].y *= s; wk[k].z *= s; wk[k].w *= s;
    }

    float4 acc[NCH];
#pragma unroll
    for (int j = 0; j < NCH; ++j) {
        float4 a = make_float4(0.f, 0.f, 0.f, 0.f);
#pragma unroll
        for (int r = 0; r < 3; ++r) {
            const float4 wk0 = wk[r * 3 + 0];
            const float4 wk1 = wk[r * 3 + 1];
            const float4 wk2 = wk[r * 3 + 2];
            const float4 c = cen[j][r];
            a.x += lf[j][r] * wk0.x + c.x * wk1.x + c.y * wk2.x;
            a.y += c.x * wk0.y + c.y * wk1.y + c.z * wk2.y;
            a.z += c.y * wk0.z + c.z * wk1.z + c.w * wk2.z;
            a.w += c.z * wk0.w + c.w * wk1.w + rf[j][r] * wk2.w;
        }
        acc[j] = a;
    }

#pragma unroll
    for (int j = 0; j < NCH; ++j)
        *reinterpret_cast<float4*>(out + base + (p * NCH + j) * Gn * HWn) = acc[j];
}

extern "C" void kernel_launch(void* const* d_in, const int* in_sizes, int n_in,
                              void* d_out, int out_size) {
    const float* x = (const float*)d_in[0];   // (8,256,56,56)
    const float* w = (const float*)d_in[1];   // (8,32,9,56,56)
    float* out = (float*)d_out;               // (8,256,56,56)

    const int threads = 128;
    const int blocks = TOTAL_THREADS / threads;  // 6272
    SKA_20950850470021_kernel<<<blocks, threads>>>(x, w, out);
}